// round 1
// baseline (speedup 1.0000x reference)
#include <cuda_runtime.h>
#include <cstdint>

// GraphConvolutionSparse: out = adj @ (inputs @ W)
//   inputs  [16384, 512]  f32
//   adj     [16384,16384] f32
//   weights [512, 128]    f32
//   out     [16384, 128]  f32
// Both GEMMs share one TF32 mma.sync kernel (N=128 fixed).

#define N_ROWS 16384
#define D_IN   512
#define D_OUT  128

// Scratch for X = inputs @ W  (8 MB) — __device__ global, allocation-free.
__device__ float g_X[N_ROWS * D_OUT];

namespace {

constexpr int BM = 128, BN = 128, BK = 32;
constexpr int AS = BK + 4;          // 36 floats: stride%32==4 -> conflict-free frag loads
constexpr int BS = BN + 4;          // 132 floats: same property
constexpr int A_SZ = BM * AS;       // 4608 floats
constexpr int B_SZ = BK * BS;       // 4224 floats
constexpr int BUF  = A_SZ + B_SZ;   // per-stage floats
constexpr int SMEM_BYTES = 2 * BUF * 4;  // 70656 B double-buffered

__device__ __forceinline__ void cp_async16(uint32_t dst, const void* src) {
    asm volatile("cp.async.cg.shared.global [%0], [%1], 16;\n" :: "r"(dst), "l"(src));
}

__device__ __forceinline__ uint32_t f2tf32(float f) {
    uint32_t r;
    asm("cvt.rna.tf32.f32 %0, %1;" : "=r"(r) : "f"(f));
    return r;
}

__device__ __forceinline__ void mma_tf32(float& c0, float& c1, float& c2, float& c3,
                                         uint32_t a0, uint32_t a1, uint32_t a2, uint32_t a3,
                                         uint32_t b0, uint32_t b1) {
    asm volatile(
        "mma.sync.aligned.m16n8k8.row.col.f32.tf32.tf32.f32 "
        "{%0,%1,%2,%3}, {%4,%5,%6,%7}, {%8,%9}, {%0,%1,%2,%3};"
        : "+f"(c0), "+f"(c1), "+f"(c2), "+f"(c3)
        : "r"(a0), "r"(a1), "r"(a2), "r"(a3), "r"(b0), "r"(b1));
}

} // namespace

// C[M,128] = A[M,K] @ B[K,128], all row-major. gridDim.x = M/128, 256 threads.
__global__ __launch_bounds__(256, 1)
void gemm_tf32_kernel(float* __restrict__ C, const float* __restrict__ A,
                      const float* __restrict__ B, int K, int lda) {
    extern __shared__ float smem[];
    const int tid  = threadIdx.x;
    const int warp = tid >> 5, lane = tid & 31;
    const int wr = warp >> 2;          // 0..1  (warp row: 64 rows each)
    const int wc = warp & 3;           // 0..3  (warp col: 32 cols each)
    const int gid = lane >> 2, tig = lane & 3;
    const int m0 = blockIdx.x * BM;

    const uint32_t s0 = (uint32_t)__cvta_generic_to_shared(smem);
    const float* Ag = A + (size_t)m0 * lda;

    float acc[4][4][4];
    #pragma unroll
    for (int mi = 0; mi < 4; ++mi)
        #pragma unroll
        for (int ni = 0; ni < 4; ++ni)
            #pragma unroll
            for (int r = 0; r < 4; ++r)
                acc[mi][ni][r] = 0.0f;

    const int KT = K / BK;

    auto load_tile = [&](int buf, int kt) {
        const float* Ap = Ag + kt * BK;
        const float* Bp = B + (size_t)(kt * BK) * BN;
        const uint32_t sA = s0 + (uint32_t)(buf * BUF) * 4u;
        const uint32_t sB = sA + (uint32_t)A_SZ * 4u;
        #pragma unroll
        for (int l = 0; l < 4; ++l) {            // 1024 float4 for A tile
            int idx = tid + l * 256;
            int r = idx >> 3, c = (idx & 7) * 4;
            cp_async16(sA + (uint32_t)(r * AS + c) * 4u, Ap + (size_t)r * lda + c);
        }
        #pragma unroll
        for (int l = 0; l < 4; ++l) {            // 1024 float4 for B tile
            int idx = tid + l * 256;
            int r = idx >> 5, c = (idx & 31) * 4;
            cp_async16(sB + (uint32_t)(r * BS + c) * 4u, Bp + (size_t)r * BN + c);
        }
        asm volatile("cp.async.commit_group;\n" ::: "memory");
    };

    load_tile(0, 0);

    for (int kt = 0; kt < KT; ++kt) {
        const int cur = kt & 1;
        if (kt + 1 < KT) {
            load_tile(cur ^ 1, kt + 1);
            asm volatile("cp.async.wait_group 1;\n" ::: "memory");
        } else {
            asm volatile("cp.async.wait_group 0;\n" ::: "memory");
        }
        __syncthreads();

        const float* As_ = smem + cur * BUF;
        const float* Bs_ = As_ + A_SZ;

        #pragma unroll
        for (int kk = 0; kk < BK; kk += 8) {
            uint32_t a[4][4], b[4][2];
            #pragma unroll
            for (int mi = 0; mi < 4; ++mi) {
                const int r = wr * 64 + mi * 16 + gid;
                a[mi][0] = f2tf32(As_[(r    ) * AS + kk + tig    ]);
                a[mi][1] = f2tf32(As_[(r + 8) * AS + kk + tig    ]);
                a[mi][2] = f2tf32(As_[(r    ) * AS + kk + tig + 4]);
                a[mi][3] = f2tf32(As_[(r + 8) * AS + kk + tig + 4]);
            }
            #pragma unroll
            for (int ni = 0; ni < 4; ++ni) {
                const int c = wc * 32 + ni * 8 + gid;
                b[ni][0] = f2tf32(Bs_[(kk + tig    ) * BS + c]);
                b[ni][1] = f2tf32(Bs_[(kk + tig + 4) * BS + c]);
            }
            #pragma unroll
            for (int mi = 0; mi < 4; ++mi)
                #pragma unroll
                for (int ni = 0; ni < 4; ++ni)
                    mma_tf32(acc[mi][ni][0], acc[mi][ni][1], acc[mi][ni][2], acc[mi][ni][3],
                             a[mi][0], a[mi][1], a[mi][2], a[mi][3],
                             b[ni][0], b[ni][1]);
        }
        __syncthreads();
    }

    // Epilogue: c0,c1 -> (row, 2*tig..+1), c2,c3 -> (row+8, ...)
    #pragma unroll
    for (int mi = 0; mi < 4; ++mi) {
        #pragma unroll
        for (int ni = 0; ni < 4; ++ni) {
            const int row = m0 + wr * 64 + mi * 16 + gid;
            const int col = wc * 32 + ni * 8 + tig * 2;
            *(float2*)(C + (size_t)row * BN + col) =
                make_float2(acc[mi][ni][0], acc[mi][ni][1]);
            *(float2*)(C + (size_t)(row + 8) * BN + col) =
                make_float2(acc[mi][ni][2], acc[mi][ni][3]);
        }
    }
}

extern "C" void kernel_launch(void* const* d_in, const int* in_sizes, int n_in,
                              void* d_out, int out_size) {
    const float* inputs  = (const float*)d_in[0];   // [16384, 512]
    const float* adj     = (const float*)d_in[1];   // [16384, 16384]
    const float* weights = (const float*)d_in[2];   // [512, 128]
    float* out = (float*)d_out;                     // [16384, 128]

    (void)in_sizes; (void)n_in; (void)out_size;

    cudaFuncSetAttribute(gemm_tf32_kernel,
                         cudaFuncAttributeMaxDynamicSharedMemorySize, SMEM_BYTES);

    float* X = nullptr;
    cudaGetSymbolAddress((void**)&X, g_X);

    // G1: X = inputs @ W         (K=512,  lda=512)
    gemm_tf32_kernel<<<N_ROWS / BM, 256, SMEM_BYTES>>>(X, inputs, weights, D_IN, D_IN);
    // G2: out = adj @ X          (K=16384, lda=16384)
    gemm_tf32_kernel<<<N_ROWS / BM, 256, SMEM_BYTES>>>(out, adj, X, N_ROWS, N_ROWS);
}

// round 2
// speedup vs baseline: 1.0095x; 1.0095x over previous
#include <cuda_runtime.h>
#include <cstdint>

// GraphConvolutionSparse: out = adj @ (inputs @ W)
//   inputs  [16384, 512]  f32
//   adj     [16384,16384] f32
//   weights [512, 128]    f32
//   out     [16384, 128]  f32

#define N_ROWS 16384
#define D_IN   512
#define D_OUT  128

// Scratch for X = inputs @ W  (8 MB) — __device__ global, allocation-free.
__device__ float g_X[N_ROWS * D_OUT];

namespace {

constexpr int BM = 128, BN = 128, BK = 32;
constexpr int AS = BK + 4;     // 36 floats/row: 144B stride -> ldmatrix conflict-free
constexpr int BS = BN + 8;     // 136 floats/row: bank offset 8 -> B LDS conflict-free
constexpr int A_SZ = BM * AS;  // 4608 floats
constexpr int B_SZ = BK * BS;  // 4352 floats
constexpr int BUF  = A_SZ + B_SZ;
constexpr int SMEM_BYTES = 2 * BUF * 4;  // 71680 B

__device__ __forceinline__ uint32_t f2tf32(float f) {
    uint32_t r;
    asm("cvt.rna.tf32.f32 %0, %1;" : "=r"(r) : "f"(f));
    return r;
}

// ldmatrix x4 on f32 data: each m8n8.b16 tile == an 8-row x 4-f32 tile (16B rows).
// Thread t receives element (t/4, t%4) of each tile as one 32-bit reg.
__device__ __forceinline__ void ldsm_x4(uint32_t& r0, uint32_t& r1,
                                        uint32_t& r2, uint32_t& r3, uint32_t addr) {
    asm volatile("ldmatrix.sync.aligned.m8n8.x4.shared.b16 {%0,%1,%2,%3}, [%4];"
                 : "=r"(r0), "=r"(r1), "=r"(r2), "=r"(r3) : "r"(addr));
}

__device__ __forceinline__ void mma_tf32(float& c0, float& c1, float& c2, float& c3,
                                         uint32_t a0, uint32_t a1, uint32_t a2, uint32_t a3,
                                         uint32_t b0, uint32_t b1) {
    asm volatile(
        "mma.sync.aligned.m16n8k8.row.col.f32.tf32.tf32.f32 "
        "{%0,%1,%2,%3}, {%4,%5,%6,%7}, {%8,%9}, {%0,%1,%2,%3};"
        : "+f"(c0), "+f"(c1), "+f"(c2), "+f"(c3)
        : "r"(a0), "r"(a1), "r"(a2), "r"(a3), "r"(b0), "r"(b1));
}

} // namespace

// C[M,128] = A[M,K] @ B[K,128], all row-major. gridDim.x = M/128, 256 threads.
__global__ __launch_bounds__(256, 1)
void gemm_tf32_kernel(float* __restrict__ C, const float* __restrict__ A,
                      const float* __restrict__ B, int K, int lda) {
    extern __shared__ float smem[];
    const int tid  = threadIdx.x;
    const int warp = tid >> 5, lane = tid & 31;
    const int wr = warp >> 2;            // 0..1 (64 rows each)
    const int wc = warp & 3;             // 0..3 (32 cols each)
    const int gid = lane >> 2, tig = lane & 3;
    const int m0 = blockIdx.x * BM;

    const uint32_t s0 = (uint32_t)__cvta_generic_to_shared(smem);
    const float* Ag = A + (size_t)m0 * lda;

    // Global-load coordinates (4 float4 each for A and B per thread)
    const int a_r0 = tid >> 3;           // +l*32
    const int a_c  = (tid & 7) * 4;
    const int b_r0 = tid >> 5;           // +l*8
    const int b_c  = (tid & 31) * 4;

    // ldmatrix per-lane source: tile index lhi = lane>>3
    const int lm_row = wr * 64 + (lane & 7) + ((lane >> 3) & 1) * 8;
    const int lm_k   = ((lane >> 3) >> 1) * 4;

    float acc[4][4][4];
    #pragma unroll
    for (int mi = 0; mi < 4; ++mi)
        #pragma unroll
        for (int ni = 0; ni < 4; ++ni)
            #pragma unroll
            for (int r = 0; r < 4; ++r)
                acc[mi][ni][r] = 0.0f;

    const int KT = K / BK;

    float4 arg[4], brg[4];

    auto ldg_tile = [&](int kt) {
        const float* Ap = Ag + (size_t)kt * BK;
        const float* Bp = B + (size_t)(kt * BK) * BN;
        #pragma unroll
        for (int l = 0; l < 4; ++l)
            arg[l] = *(const float4*)(Ap + (size_t)(a_r0 + l * 32) * lda + a_c);
        #pragma unroll
        for (int l = 0; l < 4; ++l)
            brg[l] = *(const float4*)(Bp + (size_t)(b_r0 + l * 8) * BN + b_c);
    };

    auto sts_tile = [&](int buf) {
        float* sA = smem + buf * BUF;
        float* sB = sA + A_SZ;
        #pragma unroll
        for (int l = 0; l < 4; ++l) {
            uint4 t;
            t.x = f2tf32(arg[l].x); t.y = f2tf32(arg[l].y);
            t.z = f2tf32(arg[l].z); t.w = f2tf32(arg[l].w);
            *(uint4*)(sA + (a_r0 + l * 32) * AS + a_c) = t;
        }
        #pragma unroll
        for (int l = 0; l < 4; ++l) {
            uint4 t;
            t.x = f2tf32(brg[l].x); t.y = f2tf32(brg[l].y);
            t.z = f2tf32(brg[l].z); t.w = f2tf32(brg[l].w);
            *(uint4*)(sB + (b_r0 + l * 8) * BS + b_c) = t;
        }
    };

    auto compute = [&](int buf) {
        const uint32_t aBase = s0 + (uint32_t)(buf * BUF) * 4u
                             + (uint32_t)(lm_row * AS + lm_k) * 4u;
        const uint32_t* Bu = (const uint32_t*)(smem + buf * BUF + A_SZ);
        #pragma unroll
        for (int kk = 0; kk < BK; kk += 8) {
            uint32_t a[4][4], b[4][2];
            #pragma unroll
            for (int mi = 0; mi < 4; ++mi)
                ldsm_x4(a[mi][0], a[mi][1], a[mi][2], a[mi][3],
                        aBase + (uint32_t)(mi * 16 * AS + kk) * 4u);
            #pragma unroll
            for (int ni = 0; ni < 4; ++ni) {
                const int c = wc * 32 + ni * 8 + gid;
                b[ni][0] = Bu[(kk + tig) * BS + c];
                b[ni][1] = Bu[(kk + tig + 4) * BS + c];
            }
            #pragma unroll
            for (int mi = 0; mi < 4; ++mi)
                #pragma unroll
                for (int ni = 0; ni < 4; ++ni)
                    mma_tf32(acc[mi][ni][0], acc[mi][ni][1], acc[mi][ni][2], acc[mi][ni][3],
                             a[mi][0], a[mi][1], a[mi][2], a[mi][3],
                             b[ni][0], b[ni][1]);
        }
    };

    // Pipeline: 2-stage smem + register staging (3 tiles in flight).
    ldg_tile(0);
    sts_tile(0);
    if (KT > 1) ldg_tile(1);
    __syncthreads();

    for (int kt = 0; kt < KT; ++kt) {
        const int cur = kt & 1;
        if (kt + 1 < KT) {
            sts_tile(cur ^ 1);            // tile kt+1 (in regs) -> other buffer
            if (kt + 2 < KT) ldg_tile(kt + 2);  // prefetch tile kt+2 into regs
        }
        compute(cur);
        __syncthreads();
    }

    // Epilogue
    #pragma unroll
    for (int mi = 0; mi < 4; ++mi) {
        #pragma unroll
        for (int ni = 0; ni < 4; ++ni) {
            const int row = m0 + wr * 64 + mi * 16 + gid;
            const int col = wc * 32 + ni * 8 + tig * 2;
            *(float2*)(C + (size_t)row * BN + col) =
                make_float2(acc[mi][ni][0], acc[mi][ni][1]);
            *(float2*)(C + (size_t)(row + 8) * BN + col) =
                make_float2(acc[mi][ni][2], acc[mi][ni][3]);
        }
    }
}

extern "C" void kernel_launch(void* const* d_in, const int* in_sizes, int n_in,
                              void* d_out, int out_size) {
    const float* inputs  = (const float*)d_in[0];   // [16384, 512]
    const float* adj     = (const float*)d_in[1];   // [16384, 16384]
    const float* weights = (const float*)d_in[2];   // [512, 128]
    float* out = (float*)d_out;                     // [16384, 128]

    (void)in_sizes; (void)n_in; (void)out_size;

    cudaFuncSetAttribute(gemm_tf32_kernel,
                         cudaFuncAttributeMaxDynamicSharedMemorySize, SMEM_BYTES);

    float* X = nullptr;
    cudaGetSymbolAddress((void**)&X, g_X);

    // G1: X = inputs @ W          (K=512,   lda=512)
    gemm_tf32_kernel<<<N_ROWS / BM, 256, SMEM_BYTES>>>(X, inputs, weights, D_IN, D_IN);
    // G2: out = adj @ X           (K=16384, lda=16384)
    gemm_tf32_kernel<<<N_ROWS / BM, 256, SMEM_BYTES>>>(out, adj, X, N_ROWS, N_ROWS);
}